// round 7
// baseline (speedup 1.0000x reference)
#include <cuda_runtime.h>
#include <cuda_fp16.h>

// Quad tables: per level, per plane, per (i,j) cell: the 4 bilinear corners
// (v00,v10,v01,v11) x 2 features, packed as 8 fp16 = 16 bytes = one LDG.128.
// Levels s = {128,256,512,1024}, entries = 3*s*s each.
// Quad offsets: L0=0, L1=49152, L2=245760, L3=1032192, total 4177920 (66.8 MB).
#define NQUAD_TOTAL 4177920
__device__ uint4 g_quads[NQUAD_TOTAL];

__global__ __launch_bounds__(256) void build_quads_kernel(const float* __restrict__ table)
{
    int t = blockIdx.x * blockDim.x + threadIdx.x;
    if (t >= NQUAD_TOTAL) return;

    int s, off, fac;
    if      (t < 49152)   { s = 128;  off = 0;       fac = 8; }
    else if (t < 245760)  { s = 256;  off = 49152;   fac = 4; }
    else if (t < 1032192) { s = 512;  off = 245760;  fac = 2; }
    else                  { s = 1024; off = 1032192; fac = 1; }

    int r = t - off;
    int per_plane = s * s;             // power of two
    int pl = r / per_plane;
    int r2 = r - pl * per_plane;
    int j  = r2 / s;
    int i  = r2 - j * s;

    int i0 = min(i * fac,       1023);
    int i1 = min((i + 1) * fac, 1023);
    int j0 = min(j * fac,       1023);
    int j1 = min((j + 1) * fac, 1023);

    const float2* __restrict__ tab = (const float2*)table + (size_t)pl * (1024 * 1024);
    float2 v00 = tab[j0 * 1024 + i0];
    float2 v10 = tab[j0 * 1024 + i1];
    float2 v01 = tab[j1 * 1024 + i0];
    float2 v11 = tab[j1 * 1024 + i1];

    __half2 h0 = __floats2half2_rn(v00.x, v00.y);
    __half2 h1 = __floats2half2_rn(v10.x, v10.y);
    __half2 h2 = __floats2half2_rn(v01.x, v01.y);
    __half2 h3 = __floats2half2_rn(v11.x, v11.y);

    uint4 q;
    q.x = *reinterpret_cast<unsigned*>(&h0);
    q.y = *reinterpret_cast<unsigned*>(&h1);
    q.z = *reinterpret_cast<unsigned*>(&h2);
    q.w = *reinterpret_cast<unsigned*>(&h3);
    g_quads[t] = q;
}

__global__ __launch_bounds__(256, 6) void triplane_kernel(
    const float* __restrict__ positions,
    float* __restrict__ out,
    int B)
{
    // Per-warp staging: 32 points x 8 float4, padded stride 9 to avoid bank
    // conflicts. 8 warps x 32 x 9 x 16B = 36 KB. Warp-scoped only.
    __shared__ float4 sbuf[8][32 * 9];

    const int warp = threadIdx.x >> 5;
    const int lane = threadIdx.x & 31;

    const int blockStart = blockIdx.x * 256;
    int b  = blockStart + threadIdx.x;
    int bc = b < B ? b : (B - 1);      // clamp so loads stay in-bounds

    float pos[3];
    pos[0] = positions[3 * bc + 0];
    pos[1] = positions[3 * bc + 1];
    pos[2] = positions[3 * bc + 2];

    const int S[4]    = {128, 256, 512, 1024};
    const int QOFF[4] = {0, 49152, 245760, 1032192};

    // Process levels in pairs: 6 independent gathers in flight (MLP=6),
    // consumed before the next pair. No block barrier anywhere.
    #pragma unroll
    for (int h = 0; h < 2; h++) {
        float fr2[2][3];
        uint4 q2[2][3];

        #pragma unroll
        for (int li = 0; li < 2; li++) {
            const int L = h * 2 + li;
            const int s = S[L];
            const float sm1 = (float)s - 1.0f;

            int g[3];
            #pragma unroll
            for (int d = 0; d < 3; d++) {
                float x  = fmaf(pos[d], sm1, 0.5f);
                float gf = floorf(x);
                g[d] = (int)gf;
                fr2[li][d] = x - gf;
            }
            #pragma unroll
            for (int pl = 0; pl < 3; pl++) {
                const int a1 = (pl + 1) % 3;   // c0=[0,1,2], c1=[1,2,0]
                int idx = QOFF[L] + (pl * s + g[a1]) * s + g[pl];
                q2[li][pl] = __ldg(&g_quads[idx]);
            }
        }

        #pragma unroll
        for (int li = 0; li < 2; li++) {
            const int L = h * 2 + li;
            float acc[3][2];
            #pragma unroll
            for (int pl = 0; pl < 3; pl++) {
                const int a1 = (pl + 1) % 3;
                const float f0 = fr2[li][pl];
                const float f1 = fr2[li][a1];
                uint4 qq = q2[li][pl];
                float2 c00 = __half22float2(*reinterpret_cast<__half2*>(&qq.x));
                float2 c10 = __half22float2(*reinterpret_cast<__half2*>(&qq.y));
                float2 c01 = __half22float2(*reinterpret_cast<__half2*>(&qq.z));
                float2 c11 = __half22float2(*reinterpret_cast<__half2*>(&qq.w));

                const float w0 = 1.0f - f0;
                float l0x = fmaf(w0, c00.x, f0 * c10.x);
                float l0y = fmaf(w0, c00.y, f0 * c10.y);
                float l1x = fmaf(w0, c01.x, f0 * c11.x);
                float l1y = fmaf(w0, c01.y, f0 * c11.y);

                const float w1 = 1.0f - f1;
                acc[pl][0] = fmaf(w1, l0x, f1 * l1x);
                acc[pl][1] = fmaf(w1, l0y, f1 * l1y);
            }

            const float pr0 = acc[0][0] * acc[1][0] * acc[2][0];
            const float pr1 = acc[0][1] * acc[1][1] * acc[2][1];

            sbuf[warp][lane * 9 + L * 2 + 0] =
                make_float4(acc[0][0], acc[0][1], acc[1][0], acc[1][1]);
            sbuf[warp][lane * 9 + L * 2 + 1] =
                make_float4(acc[2][0], acc[2][1], pr0, pr1);
        }
    }

    __syncwarp();

    // Coalesced store phase, warp-scoped: this warp's 32 points = 4 KB
    // contiguous. Evict-first (__stcs) so the output stream does not evict
    // the quad table from L2.
    const int warpStart = blockStart + warp * 32;
    int vcount = B - warpStart;
    if (vcount > 32) vcount = 32;
    const int nf4 = vcount * 8;
    float4* __restrict__ of4 = (float4*)out + (size_t)warpStart * 8;

    #pragma unroll
    for (int it = 0; it < 8; it++) {
        int w4 = lane + it * 32;
        if (w4 < nf4) {
            int p  = w4 >> 3;
            int jj = w4 & 7;
            __stcs(&of4[w4], sbuf[warp][p * 9 + jj]);
        }
    }
}

extern "C" void kernel_launch(void* const* d_in, const int* in_sizes, int n_in,
                              void* d_out, int out_size) {
    const float* positions = (const float*)d_in[0];
    const float* table     = (const float*)d_in[1];
    float*       out       = (float*)d_out;

    int B = in_sizes[0] / 3;

    {
        int threads = 256;
        int blocks = (NQUAD_TOTAL + threads - 1) / threads;
        build_quads_kernel<<<blocks, threads>>>(table);
    }
    {
        int threads = 256;
        int blocks  = (B + threads - 1) / threads;
        triplane_kernel<<<blocks, threads>>>(positions, out, B);
    }
}

// round 8
// speedup vs baseline: 1.0326x; 1.0326x over previous
#include <cuda_runtime.h>
#include <cuda_fp16.h>

// Quad tables: per level, per plane, per (i,j) cell: the 4 bilinear corners
// (v00,v10,v01,v11) x 2 features, packed as 8 fp16 = 16 bytes = one LDG.128.
// Levels s = {128,256,512,1024}, entries = 3*s*s each.
// Quad offsets: L0=0, L1=49152, L2=245760, L3=1032192, total 4177920 (66.8 MB).
#define NQUAD_TOTAL 4177920
__device__ uint4 g_quads[NQUAD_TOTAL];

__global__ __launch_bounds__(256) void build_quads_kernel(const float* __restrict__ table)
{
    int t = blockIdx.x * blockDim.x + threadIdx.x;
    if (t >= NQUAD_TOTAL) return;

    int s, off, fac;
    if      (t < 49152)   { s = 128;  off = 0;       fac = 8; }
    else if (t < 245760)  { s = 256;  off = 49152;   fac = 4; }
    else if (t < 1032192) { s = 512;  off = 245760;  fac = 2; }
    else                  { s = 1024; off = 1032192; fac = 1; }

    int r = t - off;
    int per_plane = s * s;             // power of two
    int pl = r / per_plane;
    int r2 = r - pl * per_plane;
    int j  = r2 / s;
    int i  = r2 - j * s;

    int i0 = min(i * fac,       1023);
    int i1 = min((i + 1) * fac, 1023);
    int j0 = min(j * fac,       1023);
    int j1 = min((j + 1) * fac, 1023);

    const float2* __restrict__ tab = (const float2*)table + (size_t)pl * (1024 * 1024);
    float2 v00 = tab[j0 * 1024 + i0];
    float2 v10 = tab[j0 * 1024 + i1];
    float2 v01 = tab[j1 * 1024 + i0];
    float2 v11 = tab[j1 * 1024 + i1];

    __half2 h0 = __floats2half2_rn(v00.x, v00.y);
    __half2 h1 = __floats2half2_rn(v10.x, v10.y);
    __half2 h2 = __floats2half2_rn(v01.x, v01.y);
    __half2 h3 = __floats2half2_rn(v11.x, v11.y);

    uint4 q;
    q.x = *reinterpret_cast<unsigned*>(&h0);
    q.y = *reinterpret_cast<unsigned*>(&h1);
    q.z = *reinterpret_cast<unsigned*>(&h2);
    q.w = *reinterpret_cast<unsigned*>(&h3);
    g_quads[t] = q;
}

__global__ __launch_bounds__(256, 6) void triplane_kernel(
    const float* __restrict__ positions,
    float* __restrict__ out,
    int B)
{
    // Per-warp staging: 32 points x 8 float4, padded stride 9 to avoid bank
    // conflicts. 8 warps x 32 x 9 x 16B = 36 KB. Warp-scoped only (no
    // __syncthreads -> no cross-warp coupling to slow loads).
    __shared__ float4 sbuf[8][32 * 9];

    const int warp = threadIdx.x >> 5;
    const int lane = threadIdx.x & 31;

    const int blockStart = blockIdx.x * 256;
    int b  = blockStart + threadIdx.x;
    int bc = b < B ? b : (B - 1);      // clamp so loads stay in-bounds

    float pos[3];
    pos[0] = positions[3 * bc + 0];
    pos[1] = positions[3 * bc + 1];
    pos[2] = positions[3 * bc + 2];

    const int S[4]    = {128, 256, 512, 1024};
    const int QOFF[4] = {0, 49152, 245760, 1032192};

    // Proven-good pattern (R6): per level, issue 3 independent divergent
    // gathers and consume them immediately. Do NOT batch more than 3 —
    // measured twice (MLP=6, MLP=12) that front-batching collapses L1tex
    // wavefront throughput ~2x on this access pattern.
    #pragma unroll
    for (int L = 0; L < 4; L++) {
        const int s = S[L];
        const float sm1 = (float)s - 1.0f;

        int   g[3];
        float fr[3];
        #pragma unroll
        for (int d = 0; d < 3; d++) {
            float x  = fmaf(pos[d], sm1, 0.5f);
            float gf = floorf(x);
            g[d]  = (int)gf;
            fr[d] = x - gf;
        }

        uint4 q[3];
        #pragma unroll
        for (int pl = 0; pl < 3; pl++) {
            const int a1 = (pl + 1) % 3;   // c0=[0,1,2], c1=[1,2,0]
            int idx = QOFF[L] + (pl * s + g[a1]) * s + g[pl];
            q[pl] = __ldg(&g_quads[idx]);
        }

        float acc[3][2];
        #pragma unroll
        for (int pl = 0; pl < 3; pl++) {
            const int a1 = (pl + 1) % 3;
            const float f0 = fr[pl];
            const float f1 = fr[a1];
            uint4 qq = q[pl];
            float2 c00 = __half22float2(*reinterpret_cast<__half2*>(&qq.x));
            float2 c10 = __half22float2(*reinterpret_cast<__half2*>(&qq.y));
            float2 c01 = __half22float2(*reinterpret_cast<__half2*>(&qq.z));
            float2 c11 = __half22float2(*reinterpret_cast<__half2*>(&qq.w));

            const float w0 = 1.0f - f0;
            float l0x = fmaf(w0, c00.x, f0 * c10.x);
            float l0y = fmaf(w0, c00.y, f0 * c10.y);
            float l1x = fmaf(w0, c01.x, f0 * c11.x);
            float l1y = fmaf(w0, c01.y, f0 * c11.y);

            const float w1 = 1.0f - f1;
            acc[pl][0] = fmaf(w1, l0x, f1 * l1x);
            acc[pl][1] = fmaf(w1, l0y, f1 * l1y);
        }

        const float pr0 = acc[0][0] * acc[1][0] * acc[2][0];
        const float pr1 = acc[0][1] * acc[1][1] * acc[2][1];

        sbuf[warp][lane * 9 + L * 2 + 0] =
            make_float4(acc[0][0], acc[0][1], acc[1][0], acc[1][1]);
        sbuf[warp][lane * 9 + L * 2 + 1] =
            make_float4(acc[2][0], acc[2][1], pr0, pr1);
    }

    __syncwarp();

    // Coalesced store phase, warp-scoped: this warp's 32 points = 4 KB
    // contiguous. Evict-first (__stcs) so the output stream does not evict
    // the quad table from L2.
    const int warpStart = blockStart + warp * 32;
    int vcount = B - warpStart;
    if (vcount > 32) vcount = 32;
    const int nf4 = vcount * 8;
    float4* __restrict__ of4 = (float4*)out + (size_t)warpStart * 8;

    #pragma unroll
    for (int it = 0; it < 8; it++) {
        int w4 = lane + it * 32;
        if (w4 < nf4) {
            int p  = w4 >> 3;
            int jj = w4 & 7;
            __stcs(&of4[w4], sbuf[warp][p * 9 + jj]);
        }
    }
}

extern "C" void kernel_launch(void* const* d_in, const int* in_sizes, int n_in,
                              void* d_out, int out_size) {
    const float* positions = (const float*)d_in[0];
    const float* table     = (const float*)d_in[1];
    float*       out       = (float*)d_out;

    int B = in_sizes[0] / 3;

    {
        int threads = 256;
        int blocks = (NQUAD_TOTAL + threads - 1) / threads;
        build_quads_kernel<<<blocks, threads>>>(table);
    }
    {
        int threads = 256;
        int blocks  = (B + threads - 1) / threads;
        triplane_kernel<<<blocks, threads>>>(positions, out, B);
    }
}

// round 10
// speedup vs baseline: 1.7718x; 1.7159x over previous
#include <cuda_runtime.h>
#include <cuda_fp16.h>

// Quad tables: per level, per plane, per (i,j) cell: the 4 bilinear corners
// (v00,v10,v01,v11) x 2 features, packed as 8 fp16 = 16 bytes = one LDG.128.
// Levels s = {128,256,512,1024}, entries = 3*s*s each.
// Quad offsets: L0=0, L1=49152, L2=245760, L3=1032192, total 4177920 (66.8 MB).
#define NQUAD_TOTAL 4177920
__device__ uint4 g_quads[NQUAD_TOTAL];

__global__ __launch_bounds__(256) void build_quads_kernel(const float* __restrict__ table)
{
    int t = blockIdx.x * blockDim.x + threadIdx.x;
    if (t >= NQUAD_TOTAL) return;

    int s, off, fac;
    if      (t < 49152)   { s = 128;  off = 0;       fac = 8; }
    else if (t < 245760)  { s = 256;  off = 49152;   fac = 4; }
    else if (t < 1032192) { s = 512;  off = 245760;  fac = 2; }
    else                  { s = 1024; off = 1032192; fac = 1; }

    int r = t - off;
    int per_plane = s * s;             // power of two
    int pl = r / per_plane;
    int r2 = r - pl * per_plane;
    int j  = r2 / s;
    int i  = r2 - j * s;

    int i0 = min(i * fac,       1023);
    int i1 = min((i + 1) * fac, 1023);
    int j0 = min(j * fac,       1023);
    int j1 = min((j + 1) * fac, 1023);

    const float2* __restrict__ tab = (const float2*)table + (size_t)pl * (1024 * 1024);
    float2 v00 = tab[j0 * 1024 + i0];
    float2 v10 = tab[j0 * 1024 + i1];
    float2 v01 = tab[j1 * 1024 + i0];
    float2 v11 = tab[j1 * 1024 + i1];

    __half2 h0 = __floats2half2_rn(v00.x, v00.y);
    __half2 h1 = __floats2half2_rn(v10.x, v10.y);
    __half2 h2 = __floats2half2_rn(v01.x, v01.y);
    __half2 h3 = __floats2half2_rn(v11.x, v11.y);

    uint4 q;
    q.x = *reinterpret_cast<unsigned*>(&h0);
    q.y = *reinterpret_cast<unsigned*>(&h1);
    q.z = *reinterpret_cast<unsigned*>(&h2);
    q.w = *reinterpret_cast<unsigned*>(&h3);
    g_quads[t] = q;
}

// NOTE: no min-blocks clause. Forcing regs<=40 (tested twice) makes ptxas
// serialize the gather address chains and collapses throughput ~1.8x.
__global__ __launch_bounds__(256) void triplane_kernel(
    const float* __restrict__ positions,
    float* __restrict__ out,
    int B)
{
    // Per-warp staging: 32 points x 8 float4, padded stride 9 to avoid bank
    // conflicts. 8 warps x 32 x 9 x 16B = 36 KB. Warp-scoped sync only.
    __shared__ float4 sbuf[8][32 * 9];

    const int warp = threadIdx.x >> 5;
    const int lane = threadIdx.x & 31;

    const int blockStart = blockIdx.x * 256;
    int b  = blockStart + threadIdx.x;
    int bc = b < B ? b : (B - 1);      // clamp so loads stay in-bounds

    float pos[3];
    pos[0] = positions[3 * bc + 0];
    pos[1] = positions[3 * bc + 1];
    pos[2] = positions[3 * bc + 2];

    const int S[4]    = {128, 256, 512, 1024};
    const int QOFF[4] = {0, 49152, 245760, 1032192};

    // Precompute fractions and gather indices for all levels (ALU only).
    float frac[4][3];
    int   qix[4][3];
    #pragma unroll
    for (int L = 0; L < 4; L++) {
        const int s = S[L];
        const float sm1 = (float)s - 1.0f;
        int g[3];
        #pragma unroll
        for (int d = 0; d < 3; d++) {
            float x  = fmaf(pos[d], sm1, 0.5f);
            float gf = floorf(x);
            g[d] = (int)gf;
            frac[L][d] = x - gf;
        }
        #pragma unroll
        for (int pl = 0; pl < 3; pl++) {
            const int a1 = (pl + 1) % 3;   // c0=[0,1,2], c1=[1,2,0]
            qix[L][pl] = QOFF[L] + (pl * s + g[a1]) * s + g[pl];
        }
    }

    // Staggered pipeline: prologue issues level 0's gathers; each iteration
    // issues level L+1's gathers BEFORE consuming level L. Steady-state 6
    // loads in flight, but never front-batched beyond two groups of 3.
    uint4 qcur[3], qnext[3];
    #pragma unroll
    for (int pl = 0; pl < 3; pl++)
        qcur[pl] = __ldg(&g_quads[qix[0][pl]]);

    #pragma unroll
    for (int L = 0; L < 4; L++) {
        if (L < 3) {
            #pragma unroll
            for (int pl = 0; pl < 3; pl++)
                qnext[pl] = __ldg(&g_quads[qix[L + 1][pl]]);
        }

        float acc[3][2];
        #pragma unroll
        for (int pl = 0; pl < 3; pl++) {
            const int a1 = (pl + 1) % 3;
            const float f0 = frac[L][pl];
            const float f1 = frac[L][a1];
            uint4 qq = qcur[pl];
            float2 c00 = __half22float2(*reinterpret_cast<__half2*>(&qq.x));
            float2 c10 = __half22float2(*reinterpret_cast<__half2*>(&qq.y));
            float2 c01 = __half22float2(*reinterpret_cast<__half2*>(&qq.z));
            float2 c11 = __half22float2(*reinterpret_cast<__half2*>(&qq.w));

            const float w0 = 1.0f - f0;
            float l0x = fmaf(w0, c00.x, f0 * c10.x);
            float l0y = fmaf(w0, c00.y, f0 * c10.y);
            float l1x = fmaf(w0, c01.x, f0 * c11.x);
            float l1y = fmaf(w0, c01.y, f0 * c11.y);

            const float w1 = 1.0f - f1;
            acc[pl][0] = fmaf(w1, l0x, f1 * l1x);
            acc[pl][1] = fmaf(w1, l0y, f1 * l1y);
        }

        const float pr0 = acc[0][0] * acc[1][0] * acc[2][0];
        const float pr1 = acc[0][1] * acc[1][1] * acc[2][1];

        sbuf[warp][lane * 9 + L * 2 + 0] =
            make_float4(acc[0][0], acc[0][1], acc[1][0], acc[1][1]);
        sbuf[warp][lane * 9 + L * 2 + 1] =
            make_float4(acc[2][0], acc[2][1], pr0, pr1);

        #pragma unroll
        for (int pl = 0; pl < 3; pl++)
            qcur[pl] = qnext[pl];
    }

    __syncwarp();

    // Coalesced store phase, warp-scoped: this warp's 32 points = 4 KB
    // contiguous. Evict-first (__stcs) so the output stream does not evict
    // the quad table from L2.
    const int warpStart = blockStart + warp * 32;
    int vcount = B - warpStart;
    if (vcount > 32) vcount = 32;
    const int nf4 = vcount * 8;
    float4* __restrict__ of4 = (float4*)out + (size_t)warpStart * 8;

    #pragma unroll
    for (int it = 0; it < 8; it++) {
        int w4 = lane + it * 32;
        if (w4 < nf4) {
            int p  = w4 >> 3;
            int jj = w4 & 7;
            __stcs(&of4[w4], sbuf[warp][p * 9 + jj]);
        }
    }
}

extern "C" void kernel_launch(void* const* d_in, const int* in_sizes, int n_in,
                              void* d_out, int out_size) {
    const float* positions = (const float*)d_in[0];
    const float* table     = (const float*)d_in[1];
    float*       out       = (float*)d_out;

    int B = in_sizes[0] / 3;

    {
        int threads = 256;
        int blocks = (NQUAD_TOTAL + threads - 1) / threads;
        build_quads_kernel<<<blocks, threads>>>(table);
    }
    {
        int threads = 256;
        int blocks  = (B + threads - 1) / threads;
        triplane_kernel<<<blocks, threads>>>(positions, out, B);
    }
}